// round 7
// baseline (speedup 1.0000x reference)
#include <cuda_runtime.h>
#include <math.h>

// Problem dims
#define B_   128
#define T_   1024
#define IN_  256
#define H_   512
#define OUT_ 256

typedef unsigned long long u64;

// ---------------- device scratch (no allocations allowed) ----------------
__device__ float g_U[(size_t)B_ * T_ * H_];   // precomputed x@w_ih0^T + b_ih0 + b_hh0, [b*T+t][H]
__device__ float g_h0[2][B_ * H_];            // layer0 hidden, ping-pong by t&1
__device__ float g_h1[2][B_ * H_];            // layer1 hidden, ping-pong by t&1

// ---------------- f32x2 / misc helpers ----------------
__device__ __forceinline__ void fma2(u64& d, u64 a, u64 b) {
    asm("fma.rn.f32x2 %0, %1, %2, %0;" : "+l"(d) : "l"(a), "l"(b));
}
__device__ __forceinline__ float2 unpack2(u64 v) {
    float2 r; asm("mov.b64 {%0, %1}, %2;" : "=f"(r.x), "=f"(r.y) : "l"(v)); return r;
}
__device__ __forceinline__ u64 pack2(float lo, float hi) {
    u64 v; asm("mov.b64 %0, {%1, %2};" : "=l"(v) : "f"(lo), "f"(hi)); return v;
}
__device__ __forceinline__ float tanh_fast(float x) {
    float y; asm("tanh.approx.f32 %0, %1;" : "=f"(y) : "f"(x)); return y;
}

// Cluster barrier: arrive has cluster-scope RELEASE, wait has ACQUIRE.
// All threads of the CTA execute it, so it also functions as a block barrier.
__device__ __forceinline__ void cluster_sync() {
    asm volatile("barrier.cluster.arrive.aligned;" ::: "memory");
    asm volatile("barrier.cluster.wait.aligned;" ::: "memory");
}

// ---------------- init ----------------
__global__ void init_kernel(const float* __restrict__ h0in) {
    int idx = blockIdx.x * blockDim.x + threadIdx.x;
    if (idx < B_ * H_) {
        g_h0[1][idx] = h0in[idx];            // initial layer-0 state (boot-staged)
        g_h1[1][idx] = h0in[B_ * H_ + idx];  // initial layer-1 state (read at t=0)
    }
}

// ---------------- precompute GEMM: U = X @ w_ih0^T + (b_ih0 + b_hh0) ----------------
#define PG_M   128
#define PG_N   64
#define PG_K   32
#define PG_PAD 36

__global__ __launch_bounds__(256) void pre_gemm(
    const float* __restrict__ X, const float* __restrict__ W,
    const float* __restrict__ b_ih, const float* __restrict__ b_hh)
{
    __shared__ float As[PG_M * PG_PAD];
    __shared__ float Bs[PG_N * PG_PAD];

    int tx = threadIdx.x & 15;
    int ty = threadIdx.x >> 4;
    int mb = (blockIdx.x >> 3) * PG_M;
    int nb = (blockIdx.x & 7) * PG_N;

    int lk = threadIdx.x & 7;
    int lm = threadIdx.x >> 3;

    u64 acc2[8][4];
    #pragma unroll
    for (int i = 0; i < 8; i++)
        #pragma unroll
        for (int j = 0; j < 4; j++) acc2[i][j] = 0ull;

    for (int kc = 0; kc < IN_; kc += PG_K) {
        #pragma unroll
        for (int i = 0; i < 4; i++) {
            int m = lm + i * 32;
            float4 v = *(const float4*)(X + (size_t)(mb + m) * IN_ + kc + lk * 4);
            *(float4*)(As + m * PG_PAD + lk * 4) = v;
        }
        #pragma unroll
        for (int i = 0; i < 2; i++) {
            int n = lm + i * 32;
            float4 v = *(const float4*)(W + (size_t)(nb + n) * IN_ + kc + lk * 4);
            *(float4*)(Bs + n * PG_PAD + lk * 4) = v;
        }
        __syncthreads();
        #pragma unroll
        for (int kq = 0; kq < PG_K / 4; kq++) {
            ulonglong2 a2[8], b2[4];
            #pragma unroll
            for (int i = 0; i < 8; i++)
                a2[i] = *(const ulonglong2*)(As + (ty * 8 + i) * PG_PAD + kq * 4);
            #pragma unroll
            for (int j = 0; j < 4; j++)
                b2[j] = *(const ulonglong2*)(Bs + (tx + 16 * j) * PG_PAD + kq * 4);
            #pragma unroll
            for (int i = 0; i < 8; i++)
                #pragma unroll
                for (int j = 0; j < 4; j++) {
                    fma2(acc2[i][j], a2[i].x, b2[j].x);
                    fma2(acc2[i][j], a2[i].y, b2[j].y);
                }
        }
        __syncthreads();
    }

    #pragma unroll
    for (int j = 0; j < 4; j++) {
        int n = nb + tx + 16 * j;
        float bias = b_ih[n] + b_hh[n];
        #pragma unroll
        for (int i = 0; i < 8; i++) {
            int m = mb + ty * 8 + i;
            float2 f = unpack2(acc2[i][j]);
            g_U[(size_t)m * H_ + n] = f.x + f.y + bias;
        }
    }
}

// ---------------- persistent recurrent kernel ----------------
// 128 CTAs = 8 clusters of 16. Cluster g owns batch rows [16g, 16g+16); within the
// cluster, CTA nn owns output cols [32nn, 32nn+32). There are NO cross-cluster data
// deps, so the per-step sync is a 16-CTA hardware cluster barrier (not a grid barrier).
// 512 threads = 16 warps; warp w owns k-slice [32w, 32w+32). w_hh0 in REGISTERS.
// SMEM: wB1, wB2 (quad layout, 64KB each) + hs0 + hs1 (32KB each) + red (32KB).
// Schedule per step: A(reads retained hs0) -> cluster_sync -> stage hs0,hs1 -> B.
#define RNN_THREADS 512
#define NWARP 16
#define CLUSTER_N 16
#define RNN_SMEM_BYTES ((2 * 512 * 32 + 3 * 16 * 512) * 4)   // 229376 B

// SMEM-weight kloop: W4 quad layout [q][lane]; hsv [16 rows][128 quads]
__device__ __forceinline__ void kloop_smem(const ulonglong2* __restrict__ W4,
                                           const ulonglong2* __restrict__ hsv,
                                           int w, int lane, u64* __restrict__ acc) {
    #pragma unroll 2
    for (int qq = 0; qq < 8; qq++) {
        int q = w * 8 + qq;
        ulonglong2 wv = W4[q * 32 + lane];
        const ulonglong2* hq = hsv + q;
        #pragma unroll
        for (int r = 0; r < 16; r++) {
            ulonglong2 h = hq[r * 128];
            fma2(acc[r], wv.x, h.x);
            fma2(acc[r], wv.y, h.y);
        }
    }
}

// Register-weight kloop (phase A)
__device__ __forceinline__ void kloop_reg(const u64* __restrict__ wreg,
                                          const ulonglong2* __restrict__ hsv,
                                          int w, u64* __restrict__ acc) {
    #pragma unroll 2
    for (int qq = 0; qq < 8; qq++) {
        int q = w * 8 + qq;
        u64 w0 = wreg[2 * qq], w1 = wreg[2 * qq + 1];
        const ulonglong2* hq = hsv + q;
        #pragma unroll
        for (int r = 0; r < 16; r++) {
            ulonglong2 h = hq[r * 128];
            fma2(acc[r], w0, h.x);
            fma2(acc[r], w1, h.y);
        }
    }
}

__device__ __forceinline__ void stage1(float4* __restrict__ d, const float4* __restrict__ s) {
    #pragma unroll
    for (int i = 0; i < 4; i++) {
        int idx = threadIdx.x + i * RNN_THREADS;
        d[idx] = __ldcg(s + idx);
    }
}

__device__ __forceinline__ void stage2(float4* __restrict__ d0, const float4* __restrict__ s0,
                                       float4* __restrict__ d1, const float4* __restrict__ s1_) {
    float4 v0[4], v1[4];
    #pragma unroll
    for (int i = 0; i < 4; i++) v0[i] = __ldcg(s0 + threadIdx.x + i * RNN_THREADS);
    #pragma unroll
    for (int i = 0; i < 4; i++) v1[i] = __ldcg(s1_ + threadIdx.x + i * RNN_THREADS);
    #pragma unroll
    for (int i = 0; i < 4; i++) d0[threadIdx.x + i * RNN_THREADS] = v0[i];
    #pragma unroll
    for (int i = 0; i < 4; i++) d1[threadIdx.x + i * RNN_THREADS] = v1[i];
}

__global__ __launch_bounds__(RNN_THREADS, 1) __cluster_dims__(CLUSTER_N, 1, 1)
void rnn_kernel(
    const float* __restrict__ w_hh0,
    const float* __restrict__ w_ih1, const float* __restrict__ w_hh1,
    const float* __restrict__ b_ih1, const float* __restrict__ b_hh1)
{
    extern __shared__ float smem[];
    float* wB1 = smem;                    // 512*32 floats, quad layout
    float* wB2 = smem + 512 * 32;
    float* hs0 = smem + 2 * 512 * 32;     // 16 x 512
    float* hs1 = hs0 + 16 * 512;
    float* red = hs1 + 16 * 512;          // 16 x 16 x 32

    int nn = blockIdx.x & 15, bb = blockIdx.x >> 4;   // cluster = batch group bb
    int n0 = nn * 32, b0g = bb * 16;
    int w = threadIdx.x >> 5, lane = threadIdx.x & 31;

    // SMEM weights (phase B): quad layout W4[q*32 + c] = w[n0+c][4q..4q+3]
    for (int idx = threadIdx.x; idx < 128 * 32; idx += RNN_THREADS) {
        int q = idx >> 5, c = idx & 31;
        ((float4*)wB1)[idx] = *(const float4*)(w_ih1 + (size_t)(n0 + c) * H_ + 4 * q);
        ((float4*)wB2)[idx] = *(const float4*)(w_hh1 + (size_t)(n0 + c) * H_ + 4 * q);
    }
    // Register weights (phase A): this thread's col = n0+lane, k-slice [32w, 32w+32)
    u64 wreg[16];
    {
        const float4* wp = (const float4*)(w_hh0 + (size_t)(n0 + lane) * H_ + 32 * w);
        #pragma unroll
        for (int i = 0; i < 8; i++) {
            float4 v = __ldg(wp + i);
            wreg[2 * i]     = pack2(v.x, v.y);
            wreg[2 * i + 1] = pack2(v.z, v.w);
        }
    }
    float bsum = b_ih1[n0 + lane] + b_hh1[n0 + lane];

    // Boot: hs0 <- initial layer-0 hidden state
    __syncthreads();
    stage1((float4*)hs0, (const float4*)(g_h0[1] + b0g * H_));
    __syncthreads();

    const float* pU = g_U + (size_t)(b0g + w) * T_ * H_ + n0 + lane;
    float u_pre = __ldcg(pU);
    int out0 = (b0g + w) * H_ + n0 + lane;

    const ulonglong2* hs0v = (const ulonglong2*)hs0;
    const ulonglong2* hs1v = (const ulonglong2*)hs1;
    const ulonglong2* W4B1 = (const ulonglong2*)wB1;
    const ulonglong2* W4B2 = (const ulonglong2*)wB2;

    for (int t = 0; t < T_; t++) {
        int p = t & 1;

        // ---- phase A: h0[t] = tanh(U[t] + hs0 @ w_hh0^T)  (hs0 holds h0[t-1]) ----
        u64 acc[16];
        #pragma unroll
        for (int r = 0; r < 16; r++) acc[r] = 0ull;

        float u_cur = u_pre;
        if (t + 1 < T_) { pU += H_; u_pre = __ldcg(pU); }   // prefetch next U

        kloop_reg(wreg, hs0v, w, acc);
        __syncthreads();                       // s1: prev-iter red readers done
        #pragma unroll
        for (int r = 0; r < 16; r++) {
            float2 f = unpack2(acc[r]);
            red[(r * NWARP + w) * 32 + lane] = f.x + f.y;
        }
        __syncthreads();                       // s2: red visible
        {
            float s = u_cur;                   // warp w reduces row w
            #pragma unroll
            for (int j = 0; j < NWARP; j++) s += red[(w * NWARP + j) * 32 + lane];
            __stcg(&g_h0[p][out0], tanh_fast(s));
        }

        // ---- 16-CTA cluster barrier (release h0[t]; acquire peers' h0[t], h1[t-1]) ----
        cluster_sync();

        // ---- stage both B operands with one exposed latency ----
        stage2((float4*)hs0, (const float4*)(g_h0[p] + b0g * H_),
               (float4*)hs1, (const float4*)(g_h1[1 - p] + b0g * H_));
        __syncthreads();                       // s3: hs0/hs1 visible

        // ---- phase B: h1[t] = tanh(hs0 @ w_ih1^T + hs1 @ w_hh1^T + b1) ----
        #pragma unroll
        for (int r = 0; r < 16; r++) acc[r] = 0ull;
        kloop_smem(W4B1, hs0v, w, lane, acc);
        kloop_smem(W4B2, hs1v, w, lane, acc);
        #pragma unroll
        for (int r = 0; r < 16; r++) {          // red WAR vs A-read covered by cluster_sync
            float2 f = unpack2(acc[r]);
            red[(r * NWARP + w) * 32 + lane] = f.x + f.y;
        }
        __syncthreads();                       // s4: red visible
        {
            float s = bsum;
            #pragma unroll
            for (int j = 0; j < NWARP; j++) s += red[(w * NWARP + j) * 32 + lane];
            __stcg(&g_h1[p][out0], tanh_fast(s));
        }
        // hs0 retained: it IS h0[t], consumed by phase A of step t+1.
        // h1[t] release to cluster peers happens at next iteration's cluster_sync,
        // before any peer reads it in stage2 (consumed at step t+1).
    }
}

// ---------------- fc epilogue: out = h1_final @ fc_w^T + fc_b ----------------
__global__ void fc_kernel(const float* __restrict__ fc_w,
                          const float* __restrict__ fc_b,
                          float* __restrict__ out)
{
    __shared__ float hrow[H_];
    int b = blockIdx.x;
    const float* h1 = g_h1[(T_ - 1) & 1] + b * H_;   // last-step parity = 1
    for (int i = threadIdx.x; i < H_; i += 256) hrow[i] = __ldcg(&h1[i]);
    __syncthreads();

    int o = threadIdx.x;
    float acc = fc_b[o];
    const float4* w4 = (const float4*)(fc_w + (size_t)o * H_);
    #pragma unroll 4
    for (int k4 = 0; k4 < H_ / 4; k4++) {
        float4 wv = __ldg(&w4[k4]);
        acc = fmaf(wv.x, hrow[4 * k4 + 0], acc);
        acc = fmaf(wv.y, hrow[4 * k4 + 1], acc);
        acc = fmaf(wv.z, hrow[4 * k4 + 2], acc);
        acc = fmaf(wv.w, hrow[4 * k4 + 3], acc);
    }
    out[b * OUT_ + o] = acc;
}

// ---------------- launch ----------------
extern "C" void kernel_launch(void* const* d_in, const int* in_sizes, int n_in,
                              void* d_out, int out_size) {
    (void)in_sizes; (void)n_in; (void)out_size;
    const float* x     = (const float*)d_in[0];
    const float* h0in  = (const float*)d_in[1];
    const float* w_ih0 = (const float*)d_in[2];
    const float* w_hh0 = (const float*)d_in[3];
    const float* b_ih0 = (const float*)d_in[4];
    const float* b_hh0 = (const float*)d_in[5];
    const float* w_ih1 = (const float*)d_in[6];
    const float* w_hh1 = (const float*)d_in[7];
    const float* b_ih1 = (const float*)d_in[8];
    const float* b_hh1 = (const float*)d_in[9];
    const float* fc_w  = (const float*)d_in[10];
    const float* fc_b  = (const float*)d_in[11];
    float* out = (float*)d_out;

    init_kernel<<<256, 256>>>(h0in);
    pre_gemm<<<(B_ * T_ / PG_M) * (H_ / PG_N), 256>>>(x, w_ih0, b_ih0, b_hh0);
    cudaFuncSetAttribute(rnn_kernel, cudaFuncAttributeNonPortableClusterSizeAllowed, 1);
    cudaFuncSetAttribute(rnn_kernel, cudaFuncAttributeMaxDynamicSharedMemorySize, RNN_SMEM_BYTES);
    rnn_kernel<<<128, RNN_THREADS, RNN_SMEM_BYTES>>>(w_hh0, w_ih1, w_hh1, b_ih1, b_hh1);
    fc_kernel<<<B_, 256>>>(fc_w, fc_b, out);
}

// round 15
// speedup vs baseline: 1.1582x; 1.1582x over previous
#include <cuda_runtime.h>
#include <cuda_bf16.h>
#include <math.h>
#include <cstdint>

// Problem dims
#define B_   128
#define T_   1024
#define IN_  256
#define H_   512
#define OUT_ 256

typedef unsigned long long u64;

// ---------------- device scratch (no allocations allowed) ----------------
__device__ float g_U[(size_t)B_ * T_ * H_];   // precomputed x@w_ih0^T + b_ih0 + b_hh0, [b*T+t][H]
__device__ float g_h0[2][B_ * H_];            // layer0 hidden, ping-pong by t&1
__device__ float g_h1[2][B_ * H_];            // layer1 hidden, ping-pong by t&1
__device__ unsigned g_bars[256];              // 8 group barrier counters, 128B apart
__device__ __nv_bfloat16 g_Xh[(size_t)B_ * T_ * IN_];  // X split-bf16 hi
__device__ __nv_bfloat16 g_Xl[(size_t)B_ * T_ * IN_];  // X split-bf16 lo
__device__ __nv_bfloat16 g_Wh[H_ * IN_];               // w_ih0 hi
__device__ __nv_bfloat16 g_Wl[H_ * IN_];               // w_ih0 lo

// ---------------- helpers ----------------
__device__ __forceinline__ void fma2(u64& d, u64 a, u64 b) {
    asm("fma.rn.f32x2 %0, %1, %2, %0;" : "+l"(d) : "l"(a), "l"(b));
}
__device__ __forceinline__ float2 unpack2(u64 v) {
    float2 r; asm("mov.b64 {%0, %1}, %2;" : "=f"(r.x), "=f"(r.y) : "l"(v)); return r;
}
__device__ __forceinline__ u64 pack2(float lo, float hi) {
    u64 v; asm("mov.b64 %0, {%1, %2};" : "=l"(v) : "f"(lo), "f"(hi)); return v;
}
__device__ __forceinline__ float tanh_fast(float x) {
    float y; asm("tanh.approx.f32 %0, %1;" : "=f"(y) : "f"(x)); return y;
}

// ---------------- init ----------------
__global__ void init_kernel(const float* __restrict__ h0in) {
    int idx = blockIdx.x * blockDim.x + threadIdx.x;
    if (idx < 256) g_bars[idx] = 0u;
    if (idx < B_ * H_) {
        g_h0[1][idx] = h0in[idx];            // initial layer-0 state (boot-staged)
        g_h1[1][idx] = h0in[B_ * H_ + idx];  // initial layer-1 state (read at t=0)
    }
}

// ---------------- split-bf16 conversion: X and W -> (hi, lo) ----------------
// 4 floats per thread. Blocks [0, 32768) cover X; [32768, 32896) cover W.
__global__ __launch_bounds__(256) void conv_kernel(const float* __restrict__ X,
                                                   const float* __restrict__ W) {
    bool isW = blockIdx.x >= 32768;
    size_t i4 = ((size_t)(isW ? blockIdx.x - 32768 : blockIdx.x) * 256 + threadIdx.x);
    const float4* src = (const float4*)(isW ? W : X);
    __nv_bfloat16* dh = isW ? g_Wh : g_Xh;
    __nv_bfloat16* dl = isW ? g_Wl : g_Xl;
    float4 v = __ldg(src + i4);
    __nv_bfloat162 h01 = __floats2bfloat162_rn(v.x, v.y);
    __nv_bfloat162 h23 = __floats2bfloat162_rn(v.z, v.w);
    float2 f01 = __bfloat1622float2(h01);
    float2 f23 = __bfloat1622float2(h23);
    __nv_bfloat162 l01 = __floats2bfloat162_rn(v.x - f01.x, v.y - f01.y);
    __nv_bfloat162 l23 = __floats2bfloat162_rn(v.z - f23.x, v.w - f23.y);
    uint2 ph = make_uint2(*(uint32_t*)&h01, *(uint32_t*)&h23);
    uint2 pl = make_uint2(*(uint32_t*)&l01, *(uint32_t*)&l23);
    *(uint2*)(dh + 4 * i4) = ph;
    *(uint2*)(dl + 4 * i4) = pl;
}

// ---------------- precompute GEMM via mma.sync split-bf16 ----------------
// U = X @ w_ih0^T + (b_ih0 + b_hh0);  D = Xh*Wh + Xh*Wl + Xl*Wh (fp32 accum).
// CTA tile M=128 x N=64, K=256. 256 threads = 8 warps; warp w owns rows [16w,16w+16).
// SMEM rows padded to 264 bf16 (132 words): fragment loads hit all 32 banks.
#define PGW 132              // padded row width in 32-bit words
#define PG_SM_A  (128 * PGW) // words per A tile
#define PG_SM_W  (64 * PGW)
#define PG_SMEM_BYTES ((2 * PG_SM_A + 2 * PG_SM_W) * 4)   // 202752

__device__ __forceinline__ void mma16816(float* d, uint32_t a0, uint32_t a1,
                                         uint32_t a2, uint32_t a3,
                                         uint32_t b0, uint32_t b1) {
    asm("mma.sync.aligned.m16n8k16.row.col.f32.bf16.bf16.f32 "
        "{%0,%1,%2,%3}, {%4,%5,%6,%7}, {%8,%9}, {%0,%1,%2,%3};"
        : "+f"(d[0]), "+f"(d[1]), "+f"(d[2]), "+f"(d[3])
        : "r"(a0), "r"(a1), "r"(a2), "r"(a3), "r"(b0), "r"(b1));
}

__global__ __launch_bounds__(256) void pre_gemm_mma(
    const float* __restrict__ b_ih, const float* __restrict__ b_hh)
{
    extern __shared__ uint32_t smw[];
    uint32_t* Ah = smw;                      // [128][132] words (bf16x2)
    uint32_t* Al = Ah + PG_SM_A;
    uint32_t* Wh = Al + PG_SM_A;             // [64][132]
    uint32_t* Wl = Wh + PG_SM_W;

    int tid = threadIdx.x;
    int mb = (blockIdx.x >> 3) * 128;
    int nb = (blockIdx.x & 7) * 64;

    // Stage A tiles (hi+lo): 128 rows x 32 uint4 chunks per row (8 bf16 each = 256 bf16)
    for (int i = tid; i < 128 * 32; i += 256) {
        int row = i >> 5, c = i & 31;
        size_t s = (size_t)(mb + row) * IN_ + c * 8;
        *(uint4*)(Ah + row * PGW + c * 4) = *(const uint4*)(g_Xh + s);
        *(uint4*)(Al + row * PGW + c * 4) = *(const uint4*)(g_Xl + s);
    }
    // Stage W tiles: 64 rows x 32 chunks
    for (int i = tid; i < 64 * 32; i += 256) {
        int row = i >> 5, c = i & 31;
        size_t s = (size_t)(nb + row) * IN_ + c * 8;
        *(uint4*)(Wh + row * PGW + c * 4) = *(const uint4*)(g_Wh + s);
        *(uint4*)(Wl + row * PGW + c * 4) = *(const uint4*)(g_Wl + s);
    }
    __syncthreads();

    int w = tid >> 5, lane = tid & 31;
    int gid = lane >> 2, tig = lane & 3;
    int m0 = w * 16;

    float d[8][4];
    #pragma unroll
    for (int nt = 0; nt < 8; nt++)
        #pragma unroll
        for (int j = 0; j < 4; j++) d[nt][j] = 0.f;

    #pragma unroll
    for (int pass = 0; pass < 3; pass++) {
        const uint32_t* Asm = (pass == 2) ? Al : Ah;
        const uint32_t* Bsm = (pass == 1) ? Wl : Wh;
        #pragma unroll 4
        for (int kc = 0; kc < 16; kc++) {
            int kw = kc * 8 + tig;           // word offset in padded row
            uint32_t a0 = Asm[(m0 + gid) * PGW + kw];
            uint32_t a1 = Asm[(m0 + gid + 8) * PGW + kw];
            uint32_t a2 = Asm[(m0 + gid) * PGW + kw + 4];
            uint32_t a3 = Asm[(m0 + gid + 8) * PGW + kw + 4];
            #pragma unroll
            for (int nt = 0; nt < 8; nt++) {
                uint32_t b0 = Bsm[(nt * 8 + gid) * PGW + kw];
                uint32_t b1 = Bsm[(nt * 8 + gid) * PGW + kw + 4];
                mma16816(d[nt], a0, a1, a2, a3, b0, b1);
            }
        }
    }

    // Epilogue: D[m][n] + bias, f32x2 stores. Rows m0+gid, m0+gid+8; cols nt*8+tig*2.
    #pragma unroll
    for (int nt = 0; nt < 8; nt++) {
        int n = nb + nt * 8 + tig * 2;
        float bx = __ldg(&b_ih[n])     + __ldg(&b_hh[n]);
        float by = __ldg(&b_ih[n + 1]) + __ldg(&b_hh[n + 1]);
        size_t m_up = (size_t)(mb + m0 + gid);
        size_t m_dn = m_up + 8;
        *(float2*)(g_U + m_up * H_ + n) = make_float2(d[nt][0] + bx, d[nt][1] + by);
        *(float2*)(g_U + m_dn * H_ + n) = make_float2(d[nt][2] + bx, d[nt][3] + by);
    }
}

// ---------------- persistent recurrent kernel (R6 design + per-group barriers) ----------------
// 128 CTAs = 8 batch groups x 16 col tiles. Group g syncs on its OWN counter (16 CTAs) —
// no cross-group data deps exist, so groups drift independently.
#define RNN_THREADS 512
#define NWARP 16
#define RNN_SMEM_BYTES ((2 * 512 * 32 + 3 * 16 * 512) * 4)   // 229376 B

__device__ __forceinline__ void group_barrier(int gid, unsigned target) {
    __syncthreads();
    if (threadIdx.x == 0) {
        unsigned* ctr = &g_bars[gid * 32];   // 128B apart
        asm volatile("red.release.gpu.add.u32 [%0], %1;" :: "l"(ctr), "r"(1u) : "memory");
        unsigned v;
        do {
            asm volatile("ld.acquire.gpu.u32 %0, [%1];" : "=r"(v) : "l"(ctr) : "memory");
        } while (v < target);
    }
    __syncthreads();
}

__device__ __forceinline__ void kloop_smem(const ulonglong2* __restrict__ W4,
                                           const ulonglong2* __restrict__ hsv,
                                           int w, int lane, u64* __restrict__ acc) {
    #pragma unroll 2
    for (int qq = 0; qq < 8; qq++) {
        int q = w * 8 + qq;
        ulonglong2 wv = W4[q * 32 + lane];
        const ulonglong2* hq = hsv + q;
        #pragma unroll
        for (int r = 0; r < 16; r++) {
            ulonglong2 h = hq[r * 128];
            fma2(acc[r], wv.x, h.x);
            fma2(acc[r], wv.y, h.y);
        }
    }
}

__device__ __forceinline__ void kloop_reg(const u64* __restrict__ wreg,
                                          const ulonglong2* __restrict__ hsv,
                                          int w, u64* __restrict__ acc) {
    #pragma unroll 2
    for (int qq = 0; qq < 8; qq++) {
        int q = w * 8 + qq;
        u64 w0 = wreg[2 * qq], w1 = wreg[2 * qq + 1];
        const ulonglong2* hq = hsv + q;
        #pragma unroll
        for (int r = 0; r < 16; r++) {
            ulonglong2 h = hq[r * 128];
            fma2(acc[r], w0, h.x);
            fma2(acc[r], w1, h.y);
        }
    }
}

__device__ __forceinline__ void stage1(float4* __restrict__ d, const float4* __restrict__ s) {
    #pragma unroll
    for (int i = 0; i < 4; i++) {
        int idx = threadIdx.x + i * RNN_THREADS;
        d[idx] = __ldcg(s + idx);
    }
}

__device__ __forceinline__ void stage2(float4* __restrict__ d0, const float4* __restrict__ s0,
                                       float4* __restrict__ d1, const float4* __restrict__ s1_) {
    float4 v0[4], v1[4];
    #pragma unroll
    for (int i = 0; i < 4; i++) v0[i] = __ldcg(s0 + threadIdx.x + i * RNN_THREADS);
    #pragma unroll
    for (int i = 0; i < 4; i++) v1[i] = __ldcg(s1_ + threadIdx.x + i * RNN_THREADS);
    #pragma unroll
    for (int i = 0; i < 4; i++) d0[threadIdx.x + i * RNN_THREADS] = v0[i];
    #pragma unroll
    for (int i = 0; i < 4; i++) d1[threadIdx.x + i * RNN_THREADS] = v1[i];
}

__global__ __launch_bounds__(RNN_THREADS, 1) void rnn_kernel(
    const float* __restrict__ w_hh0,
    const float* __restrict__ w_ih1, const float* __restrict__ w_hh1,
    const float* __restrict__ b_ih1, const float* __restrict__ b_hh1)
{
    extern __shared__ float fsmem[];
    float* wB1 = fsmem;                    // 512*32 floats, quad layout
    float* wB2 = fsmem + 512 * 32;
    float* hs0 = fsmem + 2 * 512 * 32;     // 16 x 512
    float* hs1 = hs0 + 16 * 512;
    float* red = hs1 + 16 * 512;           // 16 x 16 x 32

    int nn = blockIdx.x & 15, bb = blockIdx.x >> 4;
    int n0 = nn * 32, b0g = bb * 16;
    int w = threadIdx.x >> 5, lane = threadIdx.x & 31;

    for (int idx = threadIdx.x; idx < 128 * 32; idx += RNN_THREADS) {
        int q = idx >> 5, c = idx & 31;
        ((float4*)wB1)[idx] = *(const float4*)(w_ih1 + (size_t)(n0 + c) * H_ + 4 * q);
        ((float4*)wB2)[idx] = *(const float4*)(w_hh1 + (size_t)(n0 + c) * H_ + 4 * q);
    }
    u64 wreg[16];
    {
        const float4* wp = (const float4*)(w_hh0 + (size_t)(n0 + lane) * H_ + 32 * w);
        #pragma unroll
        for (int i = 0; i < 8; i++) {
            float4 v = __ldg(wp + i);
            wreg[2 * i]     = pack2(v.x, v.y);
            wreg[2 * i + 1] = pack2(v.z, v.w);
        }
    }
    float bsum = b_ih1[n0 + lane] + b_hh1[n0 + lane];

    __syncthreads();
    stage1((float4*)hs0, (const float4*)(g_h0[1] + b0g * H_));
    __syncthreads();

    const float* pU = g_U + (size_t)(b0g + w) * T_ * H_ + n0 + lane;
    float u_pre = __ldcg(pU);
    int out0 = (b0g + w) * H_ + n0 + lane;

    const ulonglong2* hs0v = (const ulonglong2*)hs0;
    const ulonglong2* hs1v = (const ulonglong2*)hs1;
    const ulonglong2* W4B1 = (const ulonglong2*)wB1;
    const ulonglong2* W4B2 = (const ulonglong2*)wB2;

    for (int t = 0; t < T_; t++) {
        int p = t & 1;

        // ---- phase A: h0[t] = tanh(U[t] + hs0 @ w_hh0^T)  (hs0 holds h0[t-1]) ----
        u64 acc[16];
        #pragma unroll
        for (int r = 0; r < 16; r++) acc[r] = 0ull;

        float u_cur = u_pre;
        if (t + 1 < T_) { pU += H_; u_pre = __ldcg(pU); }

        kloop_reg(wreg, hs0v, w, acc);
        __syncthreads();                       // s1: prev-iter red readers done
        #pragma unroll
        for (int r = 0; r < 16; r++) {
            float2 f = unpack2(acc[r]);
            red[(r * NWARP + w) * 32 + lane] = f.x + f.y;
        }
        __syncthreads();                       // s2: red visible
        {
            float s = u_cur;
            #pragma unroll
            for (int j = 0; j < NWARP; j++) s += red[(w * NWARP + j) * 32 + lane];
            __stcg(&g_h0[p][out0], tanh_fast(s));
        }

        group_barrier(bb, (unsigned)(t + 1) * 16u);   // sync ONLY this batch group (16 CTAs)

        stage2((float4*)hs0, (const float4*)(g_h0[p] + b0g * H_),
               (float4*)hs1, (const float4*)(g_h1[1 - p] + b0g * H_));
        __syncthreads();                       // s3: hs0/hs1 visible

        // ---- phase B: h1[t] = tanh(hs0 @ w_ih1^T + hs1 @ w_hh1^T + b1) ----
        #pragma unroll
        for (int r = 0; r < 16; r++) acc[r] = 0ull;
        kloop_smem(W4B1, hs0v, w, lane, acc);
        kloop_smem(W4B2, hs1v, w, lane, acc);
        #pragma unroll
        for (int r = 0; r < 16; r++) {
            float2 f = unpack2(acc[r]);
            red[(r * NWARP + w) * 32 + lane] = f.x + f.y;
        }
        __syncthreads();                       // s4: red visible
        {
            float s = bsum;
            #pragma unroll
            for (int j = 0; j < NWARP; j++) s += red[(w * NWARP + j) * 32 + lane];
            __stcg(&g_h1[p][out0], tanh_fast(s));
        }
        // hs0 retained: it IS h0[t], consumed by phase A of step t+1.
    }
}

// ---------------- fc epilogue: out = h1_final @ fc_w^T + fc_b ----------------
__global__ void fc_kernel(const float* __restrict__ fc_w,
                          const float* __restrict__ fc_b,
                          float* __restrict__ out)
{
    __shared__ float hrow[H_];
    int b = blockIdx.x;
    const float* h1 = g_h1[(T_ - 1) & 1] + b * H_;
    for (int i = threadIdx.x; i < H_; i += 256) hrow[i] = __ldcg(&h1[i]);
    __syncthreads();

    int o = threadIdx.x;
    float acc = fc_b[o];
    const float4* w4 = (const float4*)(fc_w + (size_t)o * H_);
    #pragma unroll 4
    for (int k4 = 0; k4 < H_ / 4; k4++) {
        float4 wv = __ldg(&w4[k4]);
        acc = fmaf(wv.x, hrow[4 * k4 + 0], acc);
        acc = fmaf(wv.y, hrow[4 * k4 + 1], acc);
        acc = fmaf(wv.z, hrow[4 * k4 + 2], acc);
        acc = fmaf(wv.w, hrow[4 * k4 + 3], acc);
    }
    out[b * OUT_ + o] = acc;
}

// ---------------- launch ----------------
extern "C" void kernel_launch(void* const* d_in, const int* in_sizes, int n_in,
                              void* d_out, int out_size) {
    (void)in_sizes; (void)n_in; (void)out_size;
    const float* x     = (const float*)d_in[0];
    const float* h0in  = (const float*)d_in[1];
    const float* w_ih0 = (const float*)d_in[2];
    const float* w_hh0 = (const float*)d_in[3];
    const float* b_ih0 = (const float*)d_in[4];
    const float* b_hh0 = (const float*)d_in[5];
    const float* w_ih1 = (const float*)d_in[6];
    const float* w_hh1 = (const float*)d_in[7];
    const float* b_ih1 = (const float*)d_in[8];
    const float* b_hh1 = (const float*)d_in[9];
    const float* fc_w  = (const float*)d_in[10];
    const float* fc_b  = (const float*)d_in[11];
    float* out = (float*)d_out;

    init_kernel<<<256, 256>>>(h0in);
    conv_kernel<<<32768 + 128, 256>>>(x, w_ih0);
    cudaFuncSetAttribute(pre_gemm_mma, cudaFuncAttributeMaxDynamicSharedMemorySize, PG_SMEM_BYTES);
    pre_gemm_mma<<<(B_ * T_ / 128) * (H_ / 64), 256, PG_SMEM_BYTES>>>(b_ih0, b_hh0);
    cudaFuncSetAttribute(rnn_kernel, cudaFuncAttributeMaxDynamicSharedMemorySize, RNN_SMEM_BYTES);
    rnn_kernel<<<128, RNN_THREADS, RNN_SMEM_BYTES>>>(w_hh0, w_ih1, w_hh1, b_ih1, b_hh1);
    fc_kernel<<<B_, 256>>>(fc_w, fc_b, out);
}

// round 16
// speedup vs baseline: 1.7691x; 1.5274x over previous
#include <cuda_runtime.h>
#include <cuda_bf16.h>
#include <math.h>
#include <cstdint>

// Problem dims
#define B_   128
#define T_   1024
#define IN_  256
#define H_   512
#define OUT_ 256

typedef unsigned long long u64;

// ---------------- device scratch (no allocations allowed) ----------------
__device__ float g_U[(size_t)B_ * T_ * H_];   // precomputed x@w_ih0^T + b_ih0 + b_hh0, [b*T+t][H]
__device__ float g_h0[2][B_ * H_];            // layer0 hidden, ping-pong by t&1
__device__ float g_h1[2][B_ * H_];            // layer1 hidden, ping-pong by t&1
__device__ unsigned g_bar;                    // global barrier counter (R6 design)
__device__ __nv_bfloat16 g_Xh[(size_t)B_ * T_ * IN_];  // X split-bf16 hi
__device__ __nv_bfloat16 g_Xl[(size_t)B_ * T_ * IN_];  // X split-bf16 lo
__device__ __nv_bfloat16 g_Wh[H_ * IN_];               // w_ih0 hi
__device__ __nv_bfloat16 g_Wl[H_ * IN_];               // w_ih0 lo

// ---------------- helpers ----------------
__device__ __forceinline__ void fma2(u64& d, u64 a, u64 b) {
    asm("fma.rn.f32x2 %0, %1, %2, %0;" : "+l"(d) : "l"(a), "l"(b));
}
__device__ __forceinline__ float2 unpack2(u64 v) {
    float2 r; asm("mov.b64 {%0, %1}, %2;" : "=f"(r.x), "=f"(r.y) : "l"(v)); return r;
}
__device__ __forceinline__ u64 pack2(float lo, float hi) {
    u64 v; asm("mov.b64 %0, {%1, %2};" : "=l"(v) : "f"(lo), "f"(hi)); return v;
}
__device__ __forceinline__ float tanh_fast(float x) {
    float y; asm("tanh.approx.f32 %0, %1;" : "=f"(y) : "f"(x)); return y;
}

// ---------------- init ----------------
__global__ void init_kernel(const float* __restrict__ h0in) {
    int idx = blockIdx.x * blockDim.x + threadIdx.x;
    if (idx == 0) g_bar = 0u;
    if (idx < B_ * H_) {
        g_h0[1][idx] = h0in[idx];            // initial layer-0 state (boot-staged)
        g_h1[1][idx] = h0in[B_ * H_ + idx];  // initial layer-1 state (read at t=0)
    }
}

// ---------------- split-bf16 conversion: X and W -> (hi, lo) ----------------
// 4 floats per thread. Blocks [0, 32768) cover X; [32768, 32896) cover W.
__global__ __launch_bounds__(256) void conv_kernel(const float* __restrict__ X,
                                                   const float* __restrict__ W) {
    bool isW = blockIdx.x >= 32768;
    size_t i4 = ((size_t)(isW ? blockIdx.x - 32768 : blockIdx.x) * 256 + threadIdx.x);
    const float4* src = (const float4*)(isW ? W : X);
    __nv_bfloat16* dh = isW ? g_Wh : g_Xh;
    __nv_bfloat16* dl = isW ? g_Wl : g_Xl;
    float4 v = __ldg(src + i4);
    __nv_bfloat162 h01 = __floats2bfloat162_rn(v.x, v.y);
    __nv_bfloat162 h23 = __floats2bfloat162_rn(v.z, v.w);
    float2 f01 = __bfloat1622float2(h01);
    float2 f23 = __bfloat1622float2(h23);
    __nv_bfloat162 l01 = __floats2bfloat162_rn(v.x - f01.x, v.y - f01.y);
    __nv_bfloat162 l23 = __floats2bfloat162_rn(v.z - f23.x, v.w - f23.y);
    uint2 ph = make_uint2(*(uint32_t*)&h01, *(uint32_t*)&h23);
    uint2 pl = make_uint2(*(uint32_t*)&l01, *(uint32_t*)&l23);
    *(uint2*)(dh + 4 * i4) = ph;
    *(uint2*)(dl + 4 * i4) = pl;
}

// ---------------- precompute GEMM via mma.sync split-bf16 ----------------
// U = X @ w_ih0^T + (b_ih0 + b_hh0);  D = Xh*Wh + Xh*Wl + Xl*Wh (fp32 accum).
// CTA tile M=128 x N=64, K=256. 256 threads = 8 warps; warp w owns rows [16w,16w+16).
// SMEM rows padded to 264 bf16 (132 words): fragment loads hit all 32 banks.
#define PGW 132              // padded row width in 32-bit words
#define PG_SM_A  (128 * PGW) // words per A tile
#define PG_SM_W  (64 * PGW)
#define PG_SMEM_BYTES ((2 * PG_SM_A + 2 * PG_SM_W) * 4)   // 202752

__device__ __forceinline__ void mma16816(float* d, uint32_t a0, uint32_t a1,
                                         uint32_t a2, uint32_t a3,
                                         uint32_t b0, uint32_t b1) {
    asm("mma.sync.aligned.m16n8k16.row.col.f32.bf16.bf16.f32 "
        "{%0,%1,%2,%3}, {%4,%5,%6,%7}, {%8,%9}, {%0,%1,%2,%3};"
        : "+f"(d[0]), "+f"(d[1]), "+f"(d[2]), "+f"(d[3])
        : "r"(a0), "r"(a1), "r"(a2), "r"(a3), "r"(b0), "r"(b1));
}

__global__ __launch_bounds__(256) void pre_gemm_mma(
    const float* __restrict__ b_ih, const float* __restrict__ b_hh)
{
    extern __shared__ uint32_t smw[];
    uint32_t* Ah = smw;                      // [128][132] words (bf16x2)
    uint32_t* Al = Ah + PG_SM_A;
    uint32_t* Wh = Al + PG_SM_A;             // [64][132]
    uint32_t* Wl = Wh + PG_SM_W;

    int tid = threadIdx.x;
    int mb = (blockIdx.x >> 3) * 128;
    int nb = (blockIdx.x & 7) * 64;

    // Stage A tiles (hi+lo): 128 rows x 32 uint4 chunks per row (8 bf16 each = 256 bf16)
    for (int i = tid; i < 128 * 32; i += 256) {
        int row = i >> 5, c = i & 31;
        size_t s = (size_t)(mb + row) * IN_ + c * 8;
        *(uint4*)(Ah + row * PGW + c * 4) = *(const uint4*)(g_Xh + s);
        *(uint4*)(Al + row * PGW + c * 4) = *(const uint4*)(g_Xl + s);
    }
    // Stage W tiles: 64 rows x 32 chunks
    for (int i = tid; i < 64 * 32; i += 256) {
        int row = i >> 5, c = i & 31;
        size_t s = (size_t)(nb + row) * IN_ + c * 8;
        *(uint4*)(Wh + row * PGW + c * 4) = *(const uint4*)(g_Wh + s);
        *(uint4*)(Wl + row * PGW + c * 4) = *(const uint4*)(g_Wl + s);
    }
    __syncthreads();

    int w = tid >> 5, lane = tid & 31;
    int gid = lane >> 2, tig = lane & 3;
    int m0 = w * 16;

    float d[8][4];
    #pragma unroll
    for (int nt = 0; nt < 8; nt++)
        #pragma unroll
        for (int j = 0; j < 4; j++) d[nt][j] = 0.f;

    #pragma unroll
    for (int pass = 0; pass < 3; pass++) {
        const uint32_t* Asm = (pass == 2) ? Al : Ah;
        const uint32_t* Bsm = (pass == 1) ? Wl : Wh;
        #pragma unroll 4
        for (int kc = 0; kc < 16; kc++) {
            int kw = kc * 8 + tig;           // word offset in padded row
            uint32_t a0 = Asm[(m0 + gid) * PGW + kw];
            uint32_t a1 = Asm[(m0 + gid + 8) * PGW + kw];
            uint32_t a2 = Asm[(m0 + gid) * PGW + kw + 4];
            uint32_t a3 = Asm[(m0 + gid + 8) * PGW + kw + 4];
            #pragma unroll
            for (int nt = 0; nt < 8; nt++) {
                uint32_t b0 = Bsm[(nt * 8 + gid) * PGW + kw];
                uint32_t b1 = Bsm[(nt * 8 + gid) * PGW + kw + 4];
                mma16816(d[nt], a0, a1, a2, a3, b0, b1);
            }
        }
    }

    // Epilogue: D[m][n] + bias, f32x2 stores. Rows m0+gid, m0+gid+8; cols nt*8+tig*2.
    #pragma unroll
    for (int nt = 0; nt < 8; nt++) {
        int n = nb + nt * 8 + tig * 2;
        float bx = __ldg(&b_ih[n])     + __ldg(&b_hh[n]);
        float by = __ldg(&b_ih[n + 1]) + __ldg(&b_hh[n + 1]);
        size_t m_up = (size_t)(mb + m0 + gid);
        size_t m_dn = m_up + 8;
        *(float2*)(g_U + m_up * H_ + n) = make_float2(d[nt][0] + bx, d[nt][1] + by);
        *(float2*)(g_U + m_dn * H_ + n) = make_float2(d[nt][2] + bx, d[nt][3] + by);
    }
}

// ---------------- persistent recurrent kernel (EXACT R6 design: global barrier) ----------------
// 128 CTAs = 8 batch groups x 16 col tiles. 512 threads = 16 warps; warp w owns
// k-slice [32w, 32w+32). w_hh0 in REGISTERS. One GLOBAL barrier per step.
#define RNN_THREADS 512
#define NWARP 16
#define RNN_SMEM_BYTES ((2 * 512 * 32 + 3 * 16 * 512) * 4)   // 229376 B

__device__ __forceinline__ void grid_barrier(unsigned target) {
    __syncthreads();
    if (threadIdx.x == 0) {
        asm volatile("red.release.gpu.add.u32 [%0], %1;" :: "l"(&g_bar), "r"(1u) : "memory");
        unsigned v;
        do {
            asm volatile("ld.acquire.gpu.u32 %0, [%1];" : "=r"(v) : "l"(&g_bar) : "memory");
        } while (v < target);
    }
    __syncthreads();
}

__device__ __forceinline__ void kloop_smem(const ulonglong2* __restrict__ W4,
                                           const ulonglong2* __restrict__ hsv,
                                           int w, int lane, u64* __restrict__ acc) {
    #pragma unroll 2
    for (int qq = 0; qq < 8; qq++) {
        int q = w * 8 + qq;
        ulonglong2 wv = W4[q * 32 + lane];
        const ulonglong2* hq = hsv + q;
        #pragma unroll
        for (int r = 0; r < 16; r++) {
            ulonglong2 h = hq[r * 128];
            fma2(acc[r], wv.x, h.x);
            fma2(acc[r], wv.y, h.y);
        }
    }
}

__device__ __forceinline__ void kloop_reg(const u64* __restrict__ wreg,
                                          const ulonglong2* __restrict__ hsv,
                                          int w, u64* __restrict__ acc) {
    #pragma unroll 2
    for (int qq = 0; qq < 8; qq++) {
        int q = w * 8 + qq;
        u64 w0 = wreg[2 * qq], w1 = wreg[2 * qq + 1];
        const ulonglong2* hq = hsv + q;
        #pragma unroll
        for (int r = 0; r < 16; r++) {
            ulonglong2 h = hq[r * 128];
            fma2(acc[r], w0, h.x);
            fma2(acc[r], w1, h.y);
        }
    }
}

__device__ __forceinline__ void stage1(float4* __restrict__ d, const float4* __restrict__ s) {
    #pragma unroll
    for (int i = 0; i < 4; i++) {
        int idx = threadIdx.x + i * RNN_THREADS;
        d[idx] = __ldcg(s + idx);
    }
}

__device__ __forceinline__ void stage2(float4* __restrict__ d0, const float4* __restrict__ s0,
                                       float4* __restrict__ d1, const float4* __restrict__ s1_) {
    float4 v0[4], v1[4];
    #pragma unroll
    for (int i = 0; i < 4; i++) v0[i] = __ldcg(s0 + threadIdx.x + i * RNN_THREADS);
    #pragma unroll
    for (int i = 0; i < 4; i++) v1[i] = __ldcg(s1_ + threadIdx.x + i * RNN_THREADS);
    #pragma unroll
    for (int i = 0; i < 4; i++) d0[threadIdx.x + i * RNN_THREADS] = v0[i];
    #pragma unroll
    for (int i = 0; i < 4; i++) d1[threadIdx.x + i * RNN_THREADS] = v1[i];
}

__global__ __launch_bounds__(RNN_THREADS, 1) void rnn_kernel(
    const float* __restrict__ w_hh0,
    const float* __restrict__ w_ih1, const float* __restrict__ w_hh1,
    const float* __restrict__ b_ih1, const float* __restrict__ b_hh1)
{
    extern __shared__ float fsmem[];
    float* wB1 = fsmem;                    // 512*32 floats, quad layout
    float* wB2 = fsmem + 512 * 32;
    float* hs0 = fsmem + 2 * 512 * 32;     // 16 x 512
    float* hs1 = hs0 + 16 * 512;
    float* red = hs1 + 16 * 512;           // 16 x 16 x 32

    int nn = blockIdx.x & 15, bb = blockIdx.x >> 4;
    int n0 = nn * 32, b0g = bb * 16;
    int w = threadIdx.x >> 5, lane = threadIdx.x & 31;

    for (int idx = threadIdx.x; idx < 128 * 32; idx += RNN_THREADS) {
        int q = idx >> 5, c = idx & 31;
        ((float4*)wB1)[idx] = *(const float4*)(w_ih1 + (size_t)(n0 + c) * H_ + 4 * q);
        ((float4*)wB2)[idx] = *(const float4*)(w_hh1 + (size_t)(n0 + c) * H_ + 4 * q);
    }
    u64 wreg[16];
    {
        const float4* wp = (const float4*)(w_hh0 + (size_t)(n0 + lane) * H_ + 32 * w);
        #pragma unroll
        for (int i = 0; i < 8; i++) {
            float4 v = __ldg(wp + i);
            wreg[2 * i]     = pack2(v.x, v.y);
            wreg[2 * i + 1] = pack2(v.z, v.w);
        }
    }
    float bsum = b_ih1[n0 + lane] + b_hh1[n0 + lane];

    __syncthreads();
    stage1((float4*)hs0, (const float4*)(g_h0[1] + b0g * H_));
    __syncthreads();

    const float* pU = g_U + (size_t)(b0g + w) * T_ * H_ + n0 + lane;
    float u_pre = __ldcg(pU);
    int out0 = (b0g + w) * H_ + n0 + lane;

    const ulonglong2* hs0v = (const ulonglong2*)hs0;
    const ulonglong2* hs1v = (const ulonglong2*)hs1;
    const ulonglong2* W4B1 = (const ulonglong2*)wB1;
    const ulonglong2* W4B2 = (const ulonglong2*)wB2;

    for (int t = 0; t < T_; t++) {
        int p = t & 1;

        // ---- phase A: h0[t] = tanh(U[t] + hs0 @ w_hh0^T)  (hs0 holds h0[t-1]) ----
        u64 acc[16];
        #pragma unroll
        for (int r = 0; r < 16; r++) acc[r] = 0ull;

        float u_cur = u_pre;
        if (t + 1 < T_) { pU += H_; u_pre = __ldcg(pU); }

        kloop_reg(wreg, hs0v, w, acc);
        __syncthreads();                       // s1: prev-iter red readers done
        #pragma unroll
        for (int r = 0; r < 16; r++) {
            float2 f = unpack2(acc[r]);
            red[(r * NWARP + w) * 32 + lane] = f.x + f.y;
        }
        __syncthreads();                       // s2: red visible
        {
            float s = u_cur;
            #pragma unroll
            for (int j = 0; j < NWARP; j++) s += red[(w * NWARP + j) * 32 + lane];
            __stcg(&g_h0[p][out0], tanh_fast(s));
        }

        grid_barrier((unsigned)(t + 1) * 128u);  // ONE global barrier per step (R6)

        stage2((float4*)hs0, (const float4*)(g_h0[p] + b0g * H_),
               (float4*)hs1, (const float4*)(g_h1[1 - p] + b0g * H_));
        __syncthreads();                       // s3: hs0/hs1 visible

        // ---- phase B: h1[t] = tanh(hs0 @ w_ih1^T + hs1 @ w_hh1^T + b1) ----
        #pragma unroll
        for (int r = 0; r < 16; r++) acc[r] = 0ull;
        kloop_smem(W4B1, hs0v, w, lane, acc);
        kloop_smem(W4B2, hs1v, w, lane, acc);
        #pragma unroll
        for (int r = 0; r < 16; r++) {
            float2 f = unpack2(acc[r]);
            red[(r * NWARP + w) * 32 + lane] = f.x + f.y;
        }
        __syncthreads();                       // s4: red visible
        {
            float s = bsum;
            #pragma unroll
            for (int j = 0; j < NWARP; j++) s += red[(w * NWARP + j) * 32 + lane];
            __stcg(&g_h1[p][out0], tanh_fast(s));
        }
        // hs0 retained: it IS h0[t], consumed by phase A of step t+1.
    }
}

// ---------------- fc epilogue: out = h1_final @ fc_w^T + fc_b ----------------
__global__ void fc_kernel(const float* __restrict__ fc_w,
                          const float* __restrict__ fc_b,
                          float* __restrict__ out)
{
    __shared__ float hrow[H_];
    int b = blockIdx.x;
    const float* h1 = g_h1[(T_ - 1) & 1] + b * H_;
    for (int i = threadIdx.x; i < H_; i += 256) hrow[i] = __ldcg(&h1[i]);
    __syncthreads();

    int o = threadIdx.x;
    float acc = fc_b[o];
    const float4* w4 = (const float4*)(fc_w + (size_t)o * H_);
    #pragma unroll 4
    for (int k4 = 0; k4 < H_ / 4; k4++) {
        float4 wv = __ldg(&w4[k4]);
        acc = fmaf(wv.x, hrow[4 * k4 + 0], acc);
        acc = fmaf(wv.y, hrow[4 * k4 + 1], acc);
        acc = fmaf(wv.z, hrow[4 * k4 + 2], acc);
        acc = fmaf(wv.w, hrow[4 * k4 + 3], acc);
    }
    out[b * OUT_ + o] = acc;
}

// ---------------- launch ----------------
extern "C" void kernel_launch(void* const* d_in, const int* in_sizes, int n_in,
                              void* d_out, int out_size) {
    (void)in_sizes; (void)n_in; (void)out_size;
    const float* x     = (const float*)d_in[0];
    const float* h0in  = (const float*)d_in[1];
    const float* w_ih0 = (const float*)d_in[2];
    const float* w_hh0 = (const float*)d_in[3];
    const float* b_ih0 = (const float*)d_in[4];
    const float* b_hh0 = (const float*)d_in[5];
    const float* w_ih1 = (const float*)d_in[6];
    const float* w_hh1 = (const float*)d_in[7];
    const float* b_ih1 = (const float*)d_in[8];
    const float* b_hh1 = (const float*)d_in[9];
    const float* fc_w  = (const float*)d_in[10];
    const float* fc_b  = (const float*)d_in[11];
    float* out = (float*)d_out;

    init_kernel<<<256, 256>>>(h0in);
    conv_kernel<<<32768 + 128, 256>>>(x, w_ih0);
    cudaFuncSetAttribute(pre_gemm_mma, cudaFuncAttributeMaxDynamicSharedMemorySize, PG_SMEM_BYTES);
    pre_gemm_mma<<<(B_ * T_ / 128) * (H_ / 64), 256, PG_SMEM_BYTES>>>(b_ih0, b_hh0);
    cudaFuncSetAttribute(rnn_kernel, cudaFuncAttributeMaxDynamicSharedMemorySize, RNN_SMEM_BYTES);
    rnn_kernel<<<128, RNN_THREADS, RNN_SMEM_BYTES>>>(w_hh0, w_ih1, w_hh1, b_ih1, b_hh1);
    fc_kernel<<<B_, 256>>>(fc_w, fc_b, out);
}

// round 17
// speedup vs baseline: 3.7546x; 2.1223x over previous
#include <cuda_runtime.h>
#include <cuda_bf16.h>
#include <math.h>
#include <cstdint>

// Problem dims
#define B_   128
#define T_   1024
#define IN_  256
#define H_   512
#define OUT_ 256

typedef unsigned long long u64;

// ---------------- device scratch (no allocations allowed) ----------------
__device__ float g_U[(size_t)B_ * T_ * H_];   // precomputed x@w_ih0^T + b_ih0 + b_hh0, [b*T+t][H]
__device__ float g_h0[2][B_ * H_];            // layer0 hidden, ping-pong by t&1
__device__ float g_h1[2][B_ * H_];            // layer1 hidden, ping-pong by t&1
__device__ unsigned g_bar;                    // global barrier counter (R6 design)
__device__ __nv_bfloat16 g_Xh[(size_t)B_ * T_ * IN_];  // X split-bf16 hi
__device__ __nv_bfloat16 g_Xl[(size_t)B_ * T_ * IN_];  // X split-bf16 lo
__device__ __nv_bfloat16 g_Wh[H_ * IN_];               // w_ih0 hi
__device__ __nv_bfloat16 g_Wl[H_ * IN_];               // w_ih0 lo

// ---------------- helpers ----------------
__device__ __forceinline__ float tanh_fast(float x) {
    float y; asm("tanh.approx.f32 %0, %1;" : "=f"(y) : "f"(x)); return y;
}
// split float pair -> packed bf16x2 hi and lo (lo = residual)
__device__ __forceinline__ void cvt_hilo(float a, float b, uint32_t& hi, uint32_t& lo) {
    __nv_bfloat162 h = __floats2bfloat162_rn(a, b);
    float2 hf = __bfloat1622float2(h);
    __nv_bfloat162 l = __floats2bfloat162_rn(a - hf.x, b - hf.y);
    hi = *(uint32_t*)&h;
    lo = *(uint32_t*)&l;
}
__device__ __forceinline__ void mma16816(float* d, uint32_t a0, uint32_t a1,
                                         uint32_t a2, uint32_t a3,
                                         uint32_t b0, uint32_t b1) {
    asm("mma.sync.aligned.m16n8k16.row.col.f32.bf16.bf16.f32 "
        "{%0,%1,%2,%3}, {%4,%5,%6,%7}, {%8,%9}, {%0,%1,%2,%3};"
        : "+f"(d[0]), "+f"(d[1]), "+f"(d[2]), "+f"(d[3])
        : "r"(a0), "r"(a1), "r"(a2), "r"(a3), "r"(b0), "r"(b1));
}

// ---------------- init ----------------
__global__ void init_kernel(const float* __restrict__ h0in) {
    int idx = blockIdx.x * blockDim.x + threadIdx.x;
    if (idx == 0) g_bar = 0u;
    if (idx < B_ * H_) {
        g_h0[1][idx] = h0in[idx];            // initial layer-0 state (boot-staged)
        g_h1[1][idx] = h0in[B_ * H_ + idx];  // initial layer-1 state (read at t=0)
    }
}

// ---------------- split-bf16 conversion of X, w_ih0 (for pre_gemm) ----------------
__global__ __launch_bounds__(256) void conv_kernel(const float* __restrict__ X,
                                                   const float* __restrict__ W) {
    bool isW = blockIdx.x >= 32768;
    size_t i4 = ((size_t)(isW ? blockIdx.x - 32768 : blockIdx.x) * 256 + threadIdx.x);
    const float4* src = (const float4*)(isW ? W : X);
    __nv_bfloat16* dh = isW ? g_Wh : g_Xh;
    __nv_bfloat16* dl = isW ? g_Wl : g_Xl;
    float4 v = __ldg(src + i4);
    uint32_t h01, l01, h23, l23;
    cvt_hilo(v.x, v.y, h01, l01);
    cvt_hilo(v.z, v.w, h23, l23);
    *(uint2*)(dh + 4 * i4) = make_uint2(h01, h23);
    *(uint2*)(dl + 4 * i4) = make_uint2(l01, l23);
}

// ---------------- precompute GEMM via mma.sync split-bf16 (verified R15/16) ----------------
#define PGW 132
#define PG_SM_A  (128 * PGW)
#define PG_SM_W  (64 * PGW)
#define PG_SMEM_BYTES ((2 * PG_SM_A + 2 * PG_SM_W) * 4)

__global__ __launch_bounds__(256) void pre_gemm_mma(
    const float* __restrict__ b_ih, const float* __restrict__ b_hh)
{
    extern __shared__ uint32_t smw[];
    uint32_t* Ah = smw;
    uint32_t* Al = Ah + PG_SM_A;
    uint32_t* Wh = Al + PG_SM_A;
    uint32_t* Wl = Wh + PG_SM_W;

    int tid = threadIdx.x;
    int mb = (blockIdx.x >> 3) * 128;
    int nb = (blockIdx.x & 7) * 64;

    for (int i = tid; i < 128 * 32; i += 256) {
        int row = i >> 5, c = i & 31;
        size_t s = (size_t)(mb + row) * IN_ + c * 8;
        *(uint4*)(Ah + row * PGW + c * 4) = *(const uint4*)(g_Xh + s);
        *(uint4*)(Al + row * PGW + c * 4) = *(const uint4*)(g_Xl + s);
    }
    for (int i = tid; i < 64 * 32; i += 256) {
        int row = i >> 5, c = i & 31;
        size_t s = (size_t)(nb + row) * IN_ + c * 8;
        *(uint4*)(Wh + row * PGW + c * 4) = *(const uint4*)(g_Wh + s);
        *(uint4*)(Wl + row * PGW + c * 4) = *(const uint4*)(g_Wl + s);
    }
    __syncthreads();

    int w = tid >> 5, lane = tid & 31;
    int gid = lane >> 2, tig = lane & 3;
    int m0 = w * 16;

    float d[8][4];
    #pragma unroll
    for (int nt = 0; nt < 8; nt++)
        #pragma unroll
        for (int j = 0; j < 4; j++) d[nt][j] = 0.f;

    #pragma unroll
    for (int pass = 0; pass < 3; pass++) {
        const uint32_t* Asm = (pass == 2) ? Al : Ah;
        const uint32_t* Bsm = (pass == 1) ? Wl : Wh;
        #pragma unroll 4
        for (int kc = 0; kc < 16; kc++) {
            int kw = kc * 8 + tig;
            uint32_t a0 = Asm[(m0 + gid) * PGW + kw];
            uint32_t a1 = Asm[(m0 + gid + 8) * PGW + kw];
            uint32_t a2 = Asm[(m0 + gid) * PGW + kw + 4];
            uint32_t a3 = Asm[(m0 + gid + 8) * PGW + kw + 4];
            #pragma unroll
            for (int nt = 0; nt < 8; nt++) {
                uint32_t b0 = Bsm[(nt * 8 + gid) * PGW + kw];
                uint32_t b1 = Bsm[(nt * 8 + gid) * PGW + kw + 4];
                mma16816(d[nt], a0, a1, a2, a3, b0, b1);
            }
        }
    }

    #pragma unroll
    for (int nt = 0; nt < 8; nt++) {
        int n = nb + nt * 8 + tig * 2;
        float bx = __ldg(&b_ih[n])     + __ldg(&b_hh[n]);
        float by = __ldg(&b_ih[n + 1]) + __ldg(&b_hh[n + 1]);
        size_t m_up = (size_t)(mb + m0 + gid);
        size_t m_dn = m_up + 8;
        *(float2*)(g_U + m_up * H_ + n) = make_float2(d[nt][0] + bx, d[nt][1] + by);
        *(float2*)(g_U + m_dn * H_ + n) = make_float2(d[nt][2] + bx, d[nt][3] + by);
    }
}

// ---------------- persistent recurrent kernel: tensor-core split-bf16 ----------------
// 128 CTAs = 8 batch groups x 16 col tiles; CTA = 16 rows x 32 cols. 512 threads = 16 warps.
// Warp w owns k-chunks {2w, 2w+1} (32 k). Per GEMM per warp: m16n8k16 x 4 ntiles x 2 chunks
// x 3 passes (Ah*Wh + Ah*Wl + Al*Wh). w_hh0 frags in REGISTERS; w_ih1/w_hh1 bf16 hi/lo in
// SMEM (row pad 260 words -> conflict-free frag loads); h staged as bf16 hi/lo (converted
// during stage). Cross-warp k-reduce via swizzled SMEM red. Global barrier (R6-proven).
#define RNN_THREADS 512
#define PW 260                       // padded row width in words (512 bf16 = 256 + 4 pad)
// SMEM word offsets
#define SW_W1H 0
#define SW_W1L 8320
#define SW_W2H 16640
#define SW_W2L 24960
#define SW_H0H 33280
#define SW_H0L 37440
#define SW_H1H 41600
#define SW_H1L 45760
#define SW_RED 49920
#define RNN_SMEM_BYTES ((SW_RED + 16 * 512) * 4)   // 232448 = 227 KB opt-in limit
static_assert(RNN_SMEM_BYTES == 232448, "smem layout");

__device__ __forceinline__ void grid_barrier(unsigned target) {
    __syncthreads();
    if (threadIdx.x == 0) {
        asm volatile("red.release.gpu.add.u32 [%0], %1;" :: "l"(&g_bar), "r"(1u) : "memory");
        unsigned v;
        do {
            asm volatile("ld.acquire.gpu.u32 %0, [%1];" : "=r"(v) : "l"(&g_bar) : "memory");
        } while (v < target);
    }
    __syncthreads();
}

// Stage 16x512 f32 tile from global into bf16 hi/lo SMEM (pad-260 rows), converting.
// Thread (r = tid>>5, c = tid&31) covers words {c+32j}; LDG.64 coalesced, STS conflict-free.
__device__ __forceinline__ void stage_conv(uint32_t* __restrict__ dh, uint32_t* __restrict__ dl,
                                           const float* __restrict__ src) {
    int r = threadIdx.x >> 5, c = threadIdx.x & 31;
    const float2* s2 = (const float2*)(src + r * H_);
    #pragma unroll
    for (int j = 0; j < 8; j++) {
        float2 v = __ldcg(s2 + c + 32 * j);
        uint32_t hi, lo;
        cvt_hilo(v.x, v.y, hi, lo);
        dh[r * PW + c + 32 * j] = hi;
        dl[r * PW + c + 32 * j] = lo;
    }
}

// One GEMM accumulate: A (hi/lo bf16 tiles) x W (hi/lo bf16, SMEM) -> d[4][4] fp32 partials.
__device__ __forceinline__ void gemm_smem(float d[4][4],
                                          const uint32_t* __restrict__ AH, const uint32_t* __restrict__ AL,
                                          const uint32_t* __restrict__ WH, const uint32_t* __restrict__ WL,
                                          int w, int gid, int tig) {
    #pragma unroll
    for (int ci = 0; ci < 2; ci++) {
        int c = 2 * w + ci;
        int ab = gid * PW + 8 * c + tig;
        int ab2 = ab + 8 * PW;
        uint32_t ah0 = AH[ab], ah1 = AH[ab2], ah2 = AH[ab + 4], ah3 = AH[ab2 + 4];
        uint32_t al0 = AL[ab], al1 = AL[ab2], al2 = AL[ab + 4], al3 = AL[ab2 + 4];
        #pragma unroll
        for (int nt = 0; nt < 4; nt++) {
            int bi = (nt * 8 + gid) * PW + 8 * c + tig;
            uint32_t b0h = WH[bi], b1h = WH[bi + 4];
            uint32_t b0l = WL[bi], b1l = WL[bi + 4];
            mma16816(d[nt], ah0, ah1, ah2, ah3, b0h, b1h);
            mma16816(d[nt], ah0, ah1, ah2, ah3, b0l, b1l);
            mma16816(d[nt], al0, al1, al2, al3, b0h, b1h);
        }
    }
}

// Write warp partials to red with XOR swizzle (2-way max conflicts; reads conflict-free).
__device__ __forceinline__ void red_write(float* __restrict__ red, const float d[4][4],
                                          int w, int gid, int tig) {
    #pragma unroll
    for (int nt = 0; nt < 4; nt++) {
        int c0 = nt * 8 + 2 * tig;
        int sc = c0 ^ (gid << 2);
        *(float2*)&red[w * 512 + gid * 32 + sc]       = make_float2(d[nt][0], d[nt][1]);
        *(float2*)&red[w * 512 + (gid + 8) * 32 + sc] = make_float2(d[nt][2], d[nt][3]);
    }
}

__global__ __launch_bounds__(RNN_THREADS, 1) void rnn_kernel(
    const float* __restrict__ w_hh0,
    const float* __restrict__ w_ih1, const float* __restrict__ w_hh1,
    const float* __restrict__ b_ih1, const float* __restrict__ b_hh1)
{
    extern __shared__ uint32_t sm[];
    uint32_t* W1H = sm + SW_W1H;  uint32_t* W1L = sm + SW_W1L;
    uint32_t* W2H = sm + SW_W2H;  uint32_t* W2L = sm + SW_W2L;
    uint32_t* H0H = sm + SW_H0H;  uint32_t* H0L = sm + SW_H0L;
    uint32_t* H1H = sm + SW_H1H;  uint32_t* H1L = sm + SW_H1L;
    float*    red = (float*)(sm + SW_RED);

    int tid = threadIdx.x;
    int nn = blockIdx.x & 15, bb = blockIdx.x >> 4;
    int n0 = nn * 32, b0g = bb * 16;
    int w = tid >> 5, lane = tid & 31;
    int gid = lane >> 2, tig = lane & 3;

    // --- stage w_ih1 / w_hh1 as bf16 hi/lo into SMEM (once) ---
    for (int idx = tid; idx < 32 * 256; idx += RNN_THREADS) {
        int row = idx >> 8, word = idx & 255;
        int k = 2 * word;
        uint32_t hi, lo;
        const float* p1 = w_ih1 + (size_t)(n0 + row) * H_ + k;
        cvt_hilo(p1[0], p1[1], hi, lo);
        W1H[row * PW + word] = hi;  W1L[row * PW + word] = lo;
        const float* p2 = w_hh1 + (size_t)(n0 + row) * H_ + k;
        cvt_hilo(p2[0], p2[1], hi, lo);
        W2H[row * PW + word] = hi;  W2L[row * PW + word] = lo;
    }

    // --- w_hh0 fragments in registers: [chunk ci][ntile][b0/b1], hi + lo ---
    uint32_t whhH[2][4][2], whhL[2][4][2];
    #pragma unroll
    for (int ci = 0; ci < 2; ci++) {
        int c = 2 * w + ci;
        #pragma unroll
        for (int nt = 0; nt < 4; nt++) {
            const float* wr = w_hh0 + (size_t)(n0 + nt * 8 + gid) * H_ + 16 * c + 2 * tig;
            cvt_hilo(__ldg(wr),     __ldg(wr + 1), whhH[ci][nt][0], whhL[ci][nt][0]);
            cvt_hilo(__ldg(wr + 8), __ldg(wr + 9), whhH[ci][nt][1], whhL[ci][nt][1]);
        }
    }

    // Consumer mapping: thread -> output (row = tid>>5, col = tid&31)
    int crow = tid >> 5, ccol = tid & 31;
    int csc = ccol ^ ((crow & 7) << 2);
    float bsum = __ldg(&b_ih1[n0 + ccol]) + __ldg(&b_hh1[n0 + ccol]);
    const float* pU = g_U + (size_t)(b0g + crow) * T_ * H_ + n0 + ccol;
    float u_pre = __ldcg(pU);
    int out0 = (b0g + crow) * H_ + n0 + ccol;

    // Boot: convert initial h0 into H0 tiles
    __syncthreads();
    stage_conv(H0H, H0L, g_h0[1] + b0g * H_);
    __syncthreads();

    for (int t = 0; t < T_; t++) {
        int p = t & 1;

        // ---- phase A: h0[t] = tanh(U[t] + hs0 @ w_hh0^T), reg-frag weights ----
        float d[4][4];
        #pragma unroll
        for (int nt = 0; nt < 4; nt++)
            #pragma unroll
            for (int j = 0; j < 4; j++) d[nt][j] = 0.f;

        float u_cur = u_pre;
        if (t + 1 < T_) { pU += H_; u_pre = __ldcg(pU); }

        #pragma unroll
        for (int ci = 0; ci < 2; ci++) {
            int c = 2 * w + ci;
            int ab = gid * PW + 8 * c + tig;
            int ab2 = ab + 8 * PW;
            uint32_t ah0 = H0H[ab], ah1 = H0H[ab2], ah2 = H0H[ab + 4], ah3 = H0H[ab2 + 4];
            uint32_t al0 = H0L[ab], al1 = H0L[ab2], al2 = H0L[ab + 4], al3 = H0L[ab2 + 4];
            #pragma unroll
            for (int nt = 0; nt < 4; nt++) {
                mma16816(d[nt], ah0, ah1, ah2, ah3, whhH[ci][nt][0], whhH[ci][nt][1]);
                mma16816(d[nt], ah0, ah1, ah2, ah3, whhL[ci][nt][0], whhL[ci][nt][1]);
                mma16816(d[nt], al0, al1, al2, al3, whhH[ci][nt][0], whhH[ci][nt][1]);
            }
        }
        __syncthreads();                       // s1: prev phase-B red readers done
        red_write(red, d, w, gid, tig);
        __syncthreads();                       // s2: red visible
        {
            float s = u_cur;
            #pragma unroll
            for (int j = 0; j < 16; j++) s += red[j * 512 + crow * 32 + csc];
            __stcg(&g_h0[p][out0], tanh_fast(s));
        }

        grid_barrier((unsigned)(t + 1) * 128u);  // ONE global barrier per step

        // ---- stage + convert h0[t] (for B1 and next A) and h1[t-1] (for B2) ----
        stage_conv(H0H, H0L, g_h0[p] + b0g * H_);
        stage_conv(H1H, H1L, g_h1[1 - p] + b0g * H_);
        __syncthreads();                       // s3: tiles visible

        // ---- phase B: h1[t] = tanh(hs0 @ w_ih1^T + hs1 @ w_hh1^T + b1) ----
        #pragma unroll
        for (int nt = 0; nt < 4; nt++)
            #pragma unroll
            for (int j = 0; j < 4; j++) d[nt][j] = 0.f;
        gemm_smem(d, H0H, H0L, W1H, W1L, w, gid, tig);
        gemm_smem(d, H1H, H1L, W2H, W2L, w, gid, tig);
        red_write(red, d, w, gid, tig);        // red WAR vs phase-A reads covered by barrier
        __syncthreads();                       // s4: red visible
        {
            float s = bsum;
            #pragma unroll
            for (int j = 0; j < 16; j++) s += red[j * 512 + crow * 32 + csc];
            __stcg(&g_h1[p][out0], tanh_fast(s));
        }
        // H0 tiles retained: they hold h0[t], consumed by phase A of step t+1.
    }
}

// ---------------- fc epilogue: out = h1_final @ fc_w^T + fc_b ----------------
__global__ void fc_kernel(const float* __restrict__ fc_w,
                          const float* __restrict__ fc_b,
                          float* __restrict__ out)
{
    __shared__ float hrow[H_];
    int b = blockIdx.x;
    const float* h1 = g_h1[(T_ - 1) & 1] + b * H_;
    for (int i = threadIdx.x; i < H_; i += 256) hrow[i] = __ldcg(&h1[i]);
    __syncthreads();

    int o = threadIdx.x;
    float acc = fc_b[o];
    const float4* w4 = (const float4*)(fc_w + (size_t)o * H_);
    #pragma unroll 4
    for (int k4 = 0; k4 < H_ / 4; k4++) {
        float4 wv = __ldg(&w4[k4]);
        acc = fmaf(wv.x, hrow[4 * k4 + 0], acc);
        acc = fmaf(wv.y, hrow[4 * k4 + 1], acc);
        acc = fmaf(wv.z, hrow[4 * k4 + 2], acc);
        acc = fmaf(wv.w, hrow[4 * k4 + 3], acc);
    }
    out[b * OUT_ + o] = acc;
}

// ---------------- launch ----------------
extern "C" void kernel_launch(void* const* d_in, const int* in_sizes, int n_in,
                              void* d_out, int out_size) {
    (void)in_sizes; (void)n_in; (void)out_size;
    const float* x     = (const float*)d_in[0];
    const float* h0in  = (const float*)d_in[1];
    const float* w_ih0 = (const float*)d_in[2];
    const float* w_hh0 = (const float*)d_in[3];
    const float* b_ih0 = (const float*)d_in[4];
    const float* b_hh0 = (const float*)d_in[5];
    const float* w_ih1 = (const float*)d_in[6];
    const float* w_hh1 = (const float*)d_in[7];
    const float* b_ih1 = (const float*)d_in[8];
    const float* b_hh1 = (const float*)d_in[9];
    const float* fc_w  = (const float*)d_in[10];
    const float* fc_b  = (const float*)d_in[11];
    float* out = (float*)d_out;

    init_kernel<<<256, 256>>>(h0in);
    conv_kernel<<<32768 + 128, 256>>>(x, w_ih0);
    cudaFuncSetAttribute(pre_gemm_mma, cudaFuncAttributeMaxDynamicSharedMemorySize, PG_SMEM_BYTES);
    pre_gemm_mma<<<(B_ * T_ / 128) * (H_ / 64), 256, PG_SMEM_BYTES>>>(b_ih0, b_hh0);
    cudaFuncSetAttribute(rnn_kernel, cudaFuncAttributeMaxDynamicSharedMemorySize, RNN_SMEM_BYTES);
    rnn_kernel<<<128, RNN_THREADS, RNN_SMEM_BYTES>>>(w_hh0, w_ih1, w_hh1, b_ih1, b_hh1);
    fc_kernel<<<B_, 256>>>(fc_w, fc_b, out);
}